// round 2
// baseline (speedup 1.0000x reference)
#include <cuda_runtime.h>

#define NPTS 16384
#define KSUB 16
#define WD   256
#define TWF  0.2f
#define PI_F 3.14159265358979f
#define AS   260   // padded activation row stride (floats)

// smem: A(64*AS) + C(64*AS) + Wtile(32*256) + xn(128) + wn(64) + idx(64)
#define SMEM_FLOATS (64*AS*2 + 32*256 + 128 + 64 + 64)
#define SMEM_BYTES  (SMEM_FLOATS * 4)

__device__ int   g_count[KSUB];
__device__ int   g_idx[KSUB][NPTS];
__device__ float g_wn[KSUB][NPTS];

__global__ void zero_kernel(float* __restrict__ out) {
    int i = blockIdx.x * blockDim.x + threadIdx.x;
    if (i < NPTS) out[i] = 0.0f;
    if (i < KSUB) g_count[i] = 0;
}

__global__ void window_kernel(const float* __restrict__ x,
                              const float* __restrict__ xmins,
                              const float* __restrict__ xmaxs) {
    int n = blockIdx.x * blockDim.x + threadIdx.x;
    float x0 = x[2*n], x1 = x[2*n+1];
    float wr[KSUB];
    float s = 0.0f;
#pragma unroll
    for (int k = 0; k < KSUB; ++k) {
        float m0 = xmins[2*k],  m1 = xmins[2*k+1];
        float M0 = xmaxs[2*k],  M1 = xmaxs[2*k+1];
        float tl0 = fminf(fmaxf((x0 - (m0 - TWF)) * 2.5f, 0.f), 1.f);
        float tr0 = fminf(fmaxf(((M0 + TWF) - x0) * 2.5f, 0.f), 1.f);
        float tl1 = fminf(fmaxf((x1 - (m1 - TWF)) * 2.5f, 0.f), 1.f);
        float tr1 = fminf(fmaxf(((M1 + TWF) - x1) * 2.5f, 0.f), 1.f);
        float f0 = 0.25f * (1.f - cosf(PI_F*tl0)) * (1.f - cosf(PI_F*tr0));
        float f1 = 0.25f * (1.f - cosf(PI_F*tl1)) * (1.f - cosf(PI_F*tr1));
        wr[k] = f0 * f1;
        s += wr[k];
    }
    float inv = 1.0f / (s + 1e-9f);
    int lane = threadIdx.x & 31;
#pragma unroll
    for (int k = 0; k < KSUB; ++k) {
        float wn = wr[k] * inv;
        g_wn[k][n] = wn;
        bool act = (wr[k] > 0.0f);
        unsigned m = __ballot_sync(0xffffffffu, act);
        int cnt = __popc(m);
        int base = 0;
        if (lane == 0 && cnt) base = atomicAdd(&g_count[k], cnt);
        base = __shfl_sync(0xffffffffu, base, 0);
        if (act) {
            int off = __popc(m & ((1u << lane) - 1u));
            g_idx[k][base + off] = n;
        }
    }
}

__global__ void __launch_bounds__(256, 1)
mlp_kernel(const float* __restrict__ x,
           const float* __restrict__ W0, const float* __restrict__ b0,
           const float* __restrict__ W1, const float* __restrict__ b1,
           const float* __restrict__ W2, const float* __restrict__ b2,
           const float* __restrict__ W3, const float* __restrict__ b3,
           const float* __restrict__ xmins, const float* __restrict__ xmaxs,
           float* __restrict__ out) {
    extern __shared__ float sm[];
    float* bufA = sm;                       // 64*AS
    float* bufB = sm + 64*AS;               // 64*AS
    float* Ws   = sm + 2*64*AS;             // 32*256
    float* sxn  = Ws + 32*256;              // 64*2
    float* swn  = sxn + 128;                // 64
    int*   sidx = (int*)(swn + 64);         // 64

    int k   = blockIdx.y;
    int cnt = g_count[k];
    int p0  = blockIdx.x * 64;
    if (p0 >= cnt) return;
    int npts = min(64, cnt - p0);
    int tid  = threadIdx.x;

    if (tid < 64) {
        int i = g_idx[k][p0 + ((tid < npts) ? tid : 0)];
        sidx[tid] = i;
        float mn0 = xmins[2*k], mn1 = xmins[2*k+1];
        float mx0 = xmaxs[2*k], mx1 = xmaxs[2*k+1];
        float c0 = 0.5f*(mn0 + mx0), c1 = 0.5f*(mn1 + mx1);
        float s0 = fmaxf(0.5f*(mx0 - mn0), 1e-9f);
        float s1 = fmaxf(0.5f*(mx1 - mn1), 1e-9f);
        sxn[2*tid]   = (x[2*i]   - c0) / s0;
        sxn[2*tid+1] = (x[2*i+1] - c1) / s1;
        swn[tid] = g_wn[k][i];
    }
    __syncthreads();

    // ---- layer 0: [64,2] @ [2,256] + b, tanh -> bufA ----
    {
        const float* W0k = W0 + k*(2*WD);
        float w0a = W0k[tid], w0b = W0k[WD + tid], bb = b0[k*WD + tid];
#pragma unroll 4
        for (int p = 0; p < 64; ++p) {
            float v = sxn[2*p]*w0a + sxn[2*p+1]*w0b + bb;
            bufA[p*AS + tid] = tanhf(v);
        }
    }
    __syncthreads();

    // ---- layers 1 & 2: [64,256] @ [256,256] + b, tanh ----
    int cr = tid & 15, pr = tid >> 4;     // thread = (4 points) x (16 strided cols)
    const float* Wg_arr[2] = {W1 + k*WD*WD, W2 + k*WD*WD};
    const float* bg_arr[2] = {b1 + k*WD,    b2 + k*WD};
    float* A = bufA; float* C = bufB;
    for (int layer = 0; layer < 2; ++layer) {
        const float* Wg = Wg_arr[layer];
        const float* bg = bg_arr[layer];
        float acc[4][16];
#pragma unroll
        for (int j = 0; j < 16; ++j) {
            float bb = bg[cr + 16*j];
            acc[0][j] = bb; acc[1][j] = bb; acc[2][j] = bb; acc[3][j] = bb;
        }
        for (int kt = 0; kt < WD; kt += 32) {
            // stage 32x256 weight tile (rows = inner dim)
            const float4* src = (const float4*)(Wg + kt*WD);
            float4* dst = (float4*)Ws;
#pragma unroll
            for (int q = 0; q < 8; ++q)
                dst[tid + q*256] = src[tid + q*256];
            __syncthreads();
#pragma unroll
            for (int kk = 0; kk < 32; ++kk) {
                float a0 = A[(pr*4+0)*AS + kt+kk];
                float a1 = A[(pr*4+1)*AS + kt+kk];
                float a2 = A[(pr*4+2)*AS + kt+kk];
                float a3 = A[(pr*4+3)*AS + kt+kk];
#pragma unroll
                for (int j = 0; j < 16; ++j) {
                    float w = Ws[kk*WD + cr + 16*j];
                    acc[0][j] += a0*w;
                    acc[1][j] += a1*w;
                    acc[2][j] += a2*w;
                    acc[3][j] += a3*w;
                }
            }
            __syncthreads();
        }
#pragma unroll
        for (int i2 = 0; i2 < 4; ++i2)
#pragma unroll
            for (int j = 0; j < 16; ++j)
                C[(pr*4+i2)*AS + cr + 16*j] = tanhf(acc[i2][j]);
        __syncthreads();
        float* tswap = A; A = C; C = tswap;
    }

    // ---- layer 3: [64,256] @ [256,1] + b3, window-weighted atomic combine ----
    {
        const float* W3k = W3 + k*WD;
        int p = tid >> 2, s = tid & 3;
        float partial = 0.0f;
        int cbase = s * 64;
#pragma unroll 8
        for (int cc = 0; cc < 64; ++cc)
            partial += A[p*AS + cbase + cc] * W3k[cbase + cc];
        partial += __shfl_down_sync(0xffffffffu, partial, 2, 4);
        partial += __shfl_down_sync(0xffffffffu, partial, 1, 4);
        if (s == 0 && p < npts)
            atomicAdd(out + sidx[p], swn[p] * (partial + b3[k]));
    }
}

extern "C" void kernel_launch(void* const* d_in, const int* in_sizes, int n_in,
                              void* d_out, int out_size) {
    const float* x     = (const float*)d_in[0];
    const float* W0    = (const float*)d_in[1];
    const float* b0    = (const float*)d_in[2];
    const float* W1    = (const float*)d_in[3];
    const float* b1    = (const float*)d_in[4];
    const float* W2    = (const float*)d_in[5];
    const float* b2    = (const float*)d_in[6];
    const float* W3    = (const float*)d_in[7];
    const float* b3    = (const float*)d_in[8];
    const float* xmins = (const float*)d_in[9];
    const float* xmaxs = (const float*)d_in[10];
    float* out = (float*)d_out;

    cudaFuncSetAttribute(mlp_kernel,
                         cudaFuncAttributeMaxDynamicSharedMemorySize, SMEM_BYTES);

    zero_kernel<<<NPTS/256, 256>>>(out);
    window_kernel<<<NPTS/256, 256>>>(x, xmins, xmaxs);
    mlp_kernel<<<dim3(NPTS/64, KSUB), 256, SMEM_BYTES>>>(
        x, W0, b0, W1, b1, W2, b2, W3, b3, xmins, xmaxs, out);
}